// round 3
// baseline (speedup 1.0000x reference)
#include <cuda_runtime.h>
#include <math.h>

// ---------------- problem dims ----------------
#define B_   8
#define L_   1024
#define D_   1024
#define E_   2048
#define S_   128
#define M_   (B_ * L_)        // 8192 rows
#define NUV  (2 * E_ + S_)    // 4224

// ---------------- device scratch (no allocations allowed) ----------------
__device__ float g_xn  [M_ * D_];       // 33.5 MB
__device__ float g_u   [M_ * E_];       // 67 MB
__device__ float g_v   [M_ * E_];       // 67 MB
__device__ float g_base[M_ * S_];       // 4 MB
__device__ float g_q   [M_ * S_];       // 4 MB
__device__ float g_k   [M_ * S_];       // 4 MB
__device__ float g_sin [L_ * 64];
__device__ float g_cos [L_ * 64];
__device__ float g_kern[B_ * L_ * L_];  // 33.5 MB
__device__ float g_attn[M_ * E_];       // 67 MB

// ---------------- rms norm ----------------
__global__ void rmsnorm_kernel(const float* __restrict__ x,
                               const float* __restrict__ g) {
    int row = blockIdx.x;
    const float4* xr = (const float4*)(x + (size_t)row * D_);
    float4 v = xr[threadIdx.x];                 // 256 threads * 4 = 1024
    float s = v.x * v.x + v.y * v.y + v.z * v.z + v.w * v.w;

    __shared__ float red[256];
    red[threadIdx.x] = s;
    __syncthreads();
    for (int off = 128; off > 0; off >>= 1) {
        if (threadIdx.x < off) red[threadIdx.x] += red[threadIdx.x + off];
        __syncthreads();
    }
    __shared__ float sc;
    if (threadIdx.x == 0) {
        float norm = sqrtf(red[0]) * 0.03125f;   // * D^-0.5
        sc = g[0] / fmaxf(norm, 1e-5f);
    }
    __syncthreads();
    float scale = sc;
    float4 o;
    o.x = v.x * scale; o.y = v.y * scale; o.z = v.z * scale; o.w = v.w * scale;
    ((float4*)(g_xn + (size_t)row * D_))[threadIdx.x] = o;
}

// ---------------- rope sin/cos table ----------------
// Replicates the reference's fp32 pipeline with correctly-rounded math:
//   inv_freq = round_f32( 10000^(j/64) )     [double pow -> f32]
//   arg      = round_f32( l * inv_freq )     [fp32 multiply]
//   sin/cos  = round_f32( sin/cos_f64(arg) ) [double trig of the f32 arg]
// Double-precision libm is immune to fast-math flags and matches glibc
// (correctly rounded) to <=1 ulp of the f32 result.
__global__ void rope_table_kernel() {
    int idx = blockIdx.x * blockDim.x + threadIdx.x;   // L_*64
    int l = idx >> 6;
    int j = idx & 63;
    float inv_freq = (float)pow(10000.0, (double)j * (1.0 / 64.0));
    float a = __fmul_rn((float)l, inv_freq);
    g_sin[idx] = (float)sin((double)a);
    g_cos[idx] = (float)cos((double)a);
}

// ---------------- gamma/beta + rope -> q, k ----------------
__global__ void rope_apply_kernel(const float* __restrict__ gamma,
                                  const float* __restrict__ beta) {
    int m = blockIdx.x;       // 0..8191
    int s = threadIdx.x;      // 0..63
    int l = m & (L_ - 1);
    float b1 = g_base[m * S_ + s];
    float b2 = g_base[m * S_ + s + 64];
    float sn = g_sin[l * 64 + s];
    float cs = g_cos[l * 64 + s];

    // q (gamma[0], beta[0])
    float q1 = b1 * gamma[s]      + beta[s];
    float q2 = b2 * gamma[s + 64] + beta[s + 64];
    g_q[m * S_ + s]      = q1 * cs - q2 * sn;
    g_q[m * S_ + s + 64] = q2 * cs + q1 * sn;
    // k (gamma[1], beta[1])
    float k1 = b1 * gamma[128 + s]      + beta[128 + s];
    float k2 = b2 * gamma[128 + s + 64] + beta[128 + s + 64];
    g_k[m * S_ + s]      = k1 * cs - k2 * sn;
    g_k[m * S_ + s + 64] = k2 * cs + k1 * sn;
}

// ---------------- shared SGEMM bodies (128x128x8, 8x8 microtile, 256 thr) ----
__device__ __forceinline__ void sgemm_body_nt(
    const float* __restrict__ A, const float* __restrict__ Bp,
    int K, int lda, int ldb, float acc[8][8],
    float* __restrict__ As, float* __restrict__ Bs)
{
    const int tid  = threadIdx.x;
    const int lrow = tid >> 1;           // 0..127
    const int lk   = (tid & 1) * 4;      // 0 or 4
    const float* Ag = A + (size_t)lrow * lda + lk;
    const float* Bg = Bp + (size_t)lrow * ldb + lk;
    const int tr = (tid >> 4) << 3;
    const int tc = (tid & 15) << 3;

    for (int k0 = 0; k0 < K; k0 += 8) {
        float4 av = *(const float4*)(Ag + k0);
        float4 bv = *(const float4*)(Bg + k0);
        As[(lk + 0) * 128 + lrow] = av.x;
        As[(lk + 1) * 128 + lrow] = av.y;
        As[(lk + 2) * 128 + lrow] = av.z;
        As[(lk + 3) * 128 + lrow] = av.w;
        Bs[(lk + 0) * 128 + lrow] = bv.x;
        Bs[(lk + 1) * 128 + lrow] = bv.y;
        Bs[(lk + 2) * 128 + lrow] = bv.z;
        Bs[(lk + 3) * 128 + lrow] = bv.w;
        __syncthreads();
#pragma unroll
        for (int kk = 0; kk < 8; ++kk) {
            float ra[8], rb[8];
            *(float4*)&ra[0] = *(const float4*)(As + kk * 128 + tr);
            *(float4*)&ra[4] = *(const float4*)(As + kk * 128 + tr + 4);
            *(float4*)&rb[0] = *(const float4*)(Bs + kk * 128 + tc);
            *(float4*)&rb[4] = *(const float4*)(Bs + kk * 128 + tc + 4);
#pragma unroll
            for (int i = 0; i < 8; i++)
#pragma unroll
                for (int j = 0; j < 8; j++)
                    acc[i][j] = fmaf(ra[i], rb[j], acc[i][j]);
        }
        __syncthreads();
    }
}

__device__ __forceinline__ void sgemm_body_nn(
    const float* __restrict__ A, const float* __restrict__ Bp,
    int K, int lda, int ldb, float acc[8][8],
    float* __restrict__ As, float* __restrict__ Bs)
{
    const int tid  = threadIdx.x;
    const int lrow = tid >> 1;
    const int lk   = (tid & 1) * 4;
    const float* Ag = A + (size_t)lrow * lda + lk;
    const int brow = tid >> 5;           // 0..7
    const int bcol = (tid & 31) * 4;     // 0..124
    const float* Bg = Bp + (size_t)brow * ldb + bcol;
    const int tr = (tid >> 4) << 3;
    const int tc = (tid & 15) << 3;

    for (int k0 = 0; k0 < K; k0 += 8) {
        float4 av = *(const float4*)(Ag + k0);
        float4 bv = *(const float4*)(Bg + (size_t)k0 * ldb);
        As[(lk + 0) * 128 + lrow] = av.x;
        As[(lk + 1) * 128 + lrow] = av.y;
        As[(lk + 2) * 128 + lrow] = av.z;
        As[(lk + 3) * 128 + lrow] = av.w;
        *(float4*)(Bs + brow * 128 + bcol) = bv;
        __syncthreads();
#pragma unroll
        for (int kk = 0; kk < 8; ++kk) {
            float ra[8], rb[8];
            *(float4*)&ra[0] = *(const float4*)(As + kk * 128 + tr);
            *(float4*)&ra[4] = *(const float4*)(As + kk * 128 + tr + 4);
            *(float4*)&rb[0] = *(const float4*)(Bs + kk * 128 + tc);
            *(float4*)&rb[4] = *(const float4*)(Bs + kk * 128 + tc + 4);
#pragma unroll
            for (int i = 0; i < 8; i++)
#pragma unroll
                for (int j = 0; j < 8; j++)
                    acc[i][j] = fmaf(ra[i], rb[j], acc[i][j]);
        }
        __syncthreads();
    }
}

// ---------------- GEMM1: uv = silu(xn @ uv_w^T), split u/v/base ----------------
__global__ __launch_bounds__(256)
void gemm1_kernel(const float* __restrict__ W) {
    __shared__ __align__(16) float As[8 * 128];
    __shared__ __align__(16) float Bs[8 * 128];
    float acc[8][8] = {};
    int bm = blockIdx.y, bn = blockIdx.x;
    sgemm_body_nt(g_xn + (size_t)bm * 128 * D_, W + (size_t)bn * 128 * D_,
                  D_, D_, D_, acc, As, Bs);
    const int tid = threadIdx.x;
    const int tr = (tid >> 4) << 3;
    const int tc = (tid & 15) << 3;
#pragma unroll
    for (int i = 0; i < 8; i++) {
        int m = bm * 128 + tr + i;
#pragma unroll
        for (int j = 0; j < 8; j++) {
            int n = bn * 128 + tc + j;
            float t = acc[i][j];
            float s = t / (1.0f + expf(-t));     // silu
            if (n < E_)            g_u[(size_t)m * E_ + n] = s;
            else if (n < 2 * E_)   g_v[(size_t)m * E_ + (n - E_)] = s;
            else                   g_base[(size_t)m * S_ + (n - 2 * E_)] = s;
        }
    }
}

// ---------------- GEMM2: qk + rel bias -> relu^2 kernel ----------------
__global__ __launch_bounds__(256)
void gemm2_kernel(const float* __restrict__ wrel) {
    __shared__ __align__(16) float As[8 * 128];
    __shared__ __align__(16) float Bs[8 * 128];
    float acc[8][8] = {};
    int b = blockIdx.z, bm = blockIdx.y, bn = blockIdx.x;
    const float* Q  = g_q + (size_t)b * L_ * S_;
    const float* Kp = g_k + (size_t)b * L_ * S_;
    sgemm_body_nt(Q + (size_t)bm * 128 * S_, Kp + (size_t)bn * 128 * S_,
                  S_, S_, S_, acc, As, Bs);
    const int tid = threadIdx.x;
    const int tr = (tid >> 4) << 3;
    const int tc = (tid & 15) << 3;
    const float sqrtS = 11.313708498984760f;   // sqrt(128)
#pragma unroll
    for (int i = 0; i < 8; i++) {
        int mi = bm * 128 + tr + i;
#pragma unroll
        for (int j = 0; j < 8; j++) {
            int nj = bn * 128 + tc + j;
            // idx[i][j] = j - i + (L-1)
            float t = acc[i][j] + wrel[nj - mi + (L_ - 1)];
            t = t / sqrtS;
            float r = fmaxf(t, 0.0f);
            g_kern[((size_t)b * L_ + mi) * L_ + nj] = r * r;
        }
    }
}

// ---------------- GEMM3: attn = kern @ v, times u ----------------
__global__ __launch_bounds__(256)
void gemm3_kernel() {
    __shared__ __align__(16) float As[8 * 128];
    __shared__ __align__(16) float Bs[8 * 128];
    float acc[8][8] = {};
    int b = blockIdx.z, bm = blockIdx.y, bn = blockIdx.x;
    const float* Kmat = g_kern + (size_t)b * L_ * L_;
    const float* V    = g_v    + (size_t)b * L_ * E_;
    sgemm_body_nn(Kmat + (size_t)bm * 128 * L_, V + bn * 128,
                  L_, L_, E_, acc, As, Bs);
    const int tid = threadIdx.x;
    const int tr = (tid >> 4) << 3;
    const int tc = (tid & 15) << 3;
#pragma unroll
    for (int i = 0; i < 8; i++) {
        int mi = bm * 128 + tr + i;
        size_t rowoff = ((size_t)b * L_ + mi) * E_;
#pragma unroll
        for (int j = 0; j < 8; j++) {
            int nj = bn * 128 + tc + j;
            g_attn[rowoff + nj] = g_u[rowoff + nj] * acc[i][j];
        }
    }
}

// ---------------- GEMM4: y = out2 @ o_w^T + x*res_scale ----------------
__global__ __launch_bounds__(256)
void gemm4_kernel(const float* __restrict__ OW,
                  const float* __restrict__ x,
                  const float* __restrict__ res_scale,
                  float* __restrict__ out) {
    __shared__ __align__(16) float As[8 * 128];
    __shared__ __align__(16) float Bs[8 * 128];
    float acc[8][8] = {};
    int bm = blockIdx.y, bn = blockIdx.x;
    sgemm_body_nt(g_attn + (size_t)bm * 128 * E_, OW + (size_t)bn * 128 * E_,
                  E_, E_, E_, acc, As, Bs);
    const int tid = threadIdx.x;
    const int tr = (tid >> 4) << 3;
    const int tc = (tid & 15) << 3;
#pragma unroll
    for (int i = 0; i < 8; i++) {
        int m = bm * 128 + tr + i;
#pragma unroll
        for (int j = 0; j < 8; j++) {
            int d = bn * 128 + tc + j;
            out[(size_t)m * D_ + d] = x[(size_t)m * D_ + d] * res_scale[d] + acc[i][j];
        }
    }
}

// ---------------- launch ----------------
extern "C" void kernel_launch(void* const* d_in, const int* in_sizes, int n_in,
                              void* d_out, int out_size) {
    const float* x         = (const float*)d_in[0];
    const float* g         = (const float*)d_in[1];
    const float* uv_w      = (const float*)d_in[2];
    const float* gamma     = (const float*)d_in[3];
    const float* beta      = (const float*)d_in[4];
    const float* w_rel     = (const float*)d_in[5];
    const float* o_w       = (const float*)d_in[6];
    const float* res_scale = (const float*)d_in[7];
    float* out = (float*)d_out;

    rmsnorm_kernel<<<M_, 256>>>(x, g);
    rope_table_kernel<<<(L_ * 64) / 256, 256>>>();
    gemm1_kernel<<<dim3(NUV / 128, M_ / 128), 256>>>(uv_w);
    rope_apply_kernel<<<M_, 64>>>(gamma, beta);
    gemm2_kernel<<<dim3(L_ / 128, L_ / 128, B_), 256>>>(w_rel);
    gemm3_kernel<<<dim3(E_ / 128, L_ / 128, B_), 256>>>();
    gemm4_kernel<<<dim3(D_ / 128, M_ / 128), 256>>>(o_w, x, res_scale, out);
}

// round 5
// speedup vs baseline: 1.5230x; 1.5230x over previous
#include <cuda_runtime.h>
#include <cuda_bf16.h>
#include <math.h>
#include <stdint.h>

// ---------------- problem dims ----------------
#define B_   8
#define L_   1024
#define D_   1024
#define E_   2048
#define S_   128
#define M_   (B_ * L_)        // 8192
#define NUV  (2 * E_ + S_)    // 4224

// ---------------- device scratch ----------------
__device__ float g_xn  [M_ * D_];
__device__ float g_u   [M_ * E_];
__device__ float g_v   [M_ * E_];
__device__ float g_vT  [M_ * E_];
__device__ float g_base[M_ * S_];
__device__ float g_q   [M_ * S_];
__device__ float g_k   [M_ * S_];
__device__ float g_sin [L_ * 64];
__device__ float g_cos [L_ * 64];
__device__ float g_kern[(size_t)B_ * L_ * L_];
__device__ float g_attn[M_ * E_];

// ---------------- bf16 split helpers ----------------
// pack bf16(x) (low half) and bf16(y) (high half); also produce residuals.
__device__ __forceinline__ void split2(float x, float y, uint32_t& hi, uint32_t& lo) {
    float hx = __bfloat162float(__float2bfloat16_rn(x));
    float hy = __bfloat162float(__float2bfloat16_rn(y));
    asm("cvt.rn.bf16x2.f32 %0, %1, %2;" : "=r"(hi) : "f"(hy), "f"(hx));
    float lx = x - hx, ly = y - hy;
    asm("cvt.rn.bf16x2.f32 %0, %1, %2;" : "=r"(lo) : "f"(ly), "f"(lx));
}

__device__ __forceinline__ void mma_bf16(float* c, const uint32_t* a, const uint32_t* b) {
    asm volatile(
        "mma.sync.aligned.m16n8k16.row.col.f32.bf16.bf16.f32 "
        "{%0,%1,%2,%3}, {%4,%5,%6,%7}, {%8,%9}, {%0,%1,%2,%3};"
        : "+f"(c[0]), "+f"(c[1]), "+f"(c[2]), "+f"(c[3])
        : "r"(a[0]), "r"(a[1]), "r"(a[2]), "r"(a[3]), "r"(b[0]), "r"(b[1]));
}

#define STR 40   // smem row stride in bf16 elements (conflict-free for frag loads)

// ---------------- core: C[128x128] = A[128xK] * B[128xK]^T (both row-major) ----
// 256 threads, 8 warps as 2x4 (warp tile 64x32). 3x bf16 compensated MMA.
// acc[mt][nt][4]: mt in 0..3 (16-row tiles within warp's 64), nt 0..3 (8-col).
__device__ __forceinline__ void gemm_core_mma(
    const float* __restrict__ A, int lda,
    const float* __restrict__ B, int ldb,
    int K, float acc[4][4][4],
    unsigned short* sAhi, unsigned short* sAlo,
    unsigned short* sBhi, unsigned short* sBlo)
{
    const int tid  = threadIdx.x;
    const int wid  = tid >> 5;
    const int lane = tid & 31;
    const int g    = lane >> 2;
    const int tig  = lane & 3;
    const int wm   = wid >> 2;   // 0..1 -> row offset wm*64
    const int wn   = wid & 3;    // 0..3 -> col offset wn*32

    const int NC = K >> 5;
    float4 ra[4], rb[4];

    // prologue: load chunk 0 (A,B tiles are 128 rows x 32 cols fp32)
#pragma unroll
    for (int r = 0; r < 4; r++) {
        int idx = tid + 256 * r;             // 0..1023
        int row = idx >> 3, c4 = idx & 7;    // col = c4*4
        ra[r] = *(const float4*)(A + (size_t)row * lda + c4 * 4);
        rb[r] = *(const float4*)(B + (size_t)row * ldb + c4 * 4);
    }

    for (int c = 0; c < NC; c++) {
        if (c > 0) __syncthreads();          // previous compute done reading smem
        // convert + store to smem
#pragma unroll
        for (int r = 0; r < 4; r++) {
            int idx = tid + 256 * r;
            int row = idx >> 3, c4 = idx & 7;
            int off = row * STR + c4 * 4;
            uint32_t h0, l0, h1, l1;
            split2(ra[r].x, ra[r].y, h0, l0);
            split2(ra[r].z, ra[r].w, h1, l1);
            *(uint32_t*)&sAhi[off]     = h0;
            *(uint32_t*)&sAhi[off + 2] = h1;
            *(uint32_t*)&sAlo[off]     = l0;
            *(uint32_t*)&sAlo[off + 2] = l1;
            split2(rb[r].x, rb[r].y, h0, l0);
            split2(rb[r].z, rb[r].w, h1, l1);
            *(uint32_t*)&sBhi[off]     = h0;
            *(uint32_t*)&sBhi[off + 2] = h1;
            *(uint32_t*)&sBlo[off]     = l0;
            *(uint32_t*)&sBlo[off + 2] = l1;
        }
        __syncthreads();
        // prefetch next chunk
        if (c + 1 < NC) {
            const float* An = A + (size_t)(c + 1) * 32;
            const float* Bn = B + (size_t)(c + 1) * 32;
#pragma unroll
            for (int r = 0; r < 4; r++) {
                int idx = tid + 256 * r;
                int row = idx >> 3, c4 = idx & 7;
                ra[r] = *(const float4*)(An + (size_t)row * lda + c4 * 4);
                rb[r] = *(const float4*)(Bn + (size_t)row * ldb + c4 * 4);
            }
        }
        // compute: two k16 sub-steps
#pragma unroll
        for (int ks = 0; ks < 2; ks++) {
            const int kb = ks * 16;
            uint32_t ah[4][4], al[4][4], bh[4][2], bl[4][2];
#pragma unroll
            for (int mt = 0; mt < 4; mt++) {
                int base = (wm * 64 + mt * 16 + g) * STR + kb + tig * 2;
                ah[mt][0] = *(uint32_t*)&sAhi[base];
                ah[mt][1] = *(uint32_t*)&sAhi[base + 8 * STR];
                ah[mt][2] = *(uint32_t*)&sAhi[base + 8];
                ah[mt][3] = *(uint32_t*)&sAhi[base + 8 * STR + 8];
                al[mt][0] = *(uint32_t*)&sAlo[base];
                al[mt][1] = *(uint32_t*)&sAlo[base + 8 * STR];
                al[mt][2] = *(uint32_t*)&sAlo[base + 8];
                al[mt][3] = *(uint32_t*)&sAlo[base + 8 * STR + 8];
            }
#pragma unroll
            for (int nt = 0; nt < 4; nt++) {
                int base = (wn * 32 + nt * 8 + g) * STR + kb + tig * 2;
                bh[nt][0] = *(uint32_t*)&sBhi[base];
                bh[nt][1] = *(uint32_t*)&sBhi[base + 8];
                bl[nt][0] = *(uint32_t*)&sBlo[base];
                bl[nt][1] = *(uint32_t*)&sBlo[base + 8];
            }
#pragma unroll
            for (int mt = 0; mt < 4; mt++)
#pragma unroll
                for (int nt = 0; nt < 4; nt++) {
                    mma_bf16(acc[mt][nt], ah[mt], bh[nt]);
                    mma_bf16(acc[mt][nt], ah[mt], bl[nt]);
                    mma_bf16(acc[mt][nt], al[mt], bh[nt]);
                }
        }
    }
    __syncthreads();
}

#define GEMM_SMEM \
    __shared__ unsigned short sAhi[128 * STR]; \
    __shared__ unsigned short sAlo[128 * STR]; \
    __shared__ unsigned short sBhi[128 * STR]; \
    __shared__ unsigned short sBlo[128 * STR];

// fragment (mt,nt) element coords: rows wm*64+mt*16+g (+8), cols wn*32+nt*8+tig*2 (+1)

// ---------------- GEMM1: uv = silu(xn @ uv_w^T), split u/v/base ------------
__global__ __launch_bounds__(256)
void gemm1_tc(const float* __restrict__ W) {
    GEMM_SMEM
    float acc[4][4][4] = {};
    int bm = blockIdx.y, bn = blockIdx.x;
    gemm_core_mma(g_xn + (size_t)bm * 128 * D_, D_,
                  W + (size_t)bn * 128 * D_, D_, D_, acc, sAhi, sAlo, sBhi, sBlo);
    const int tid = threadIdx.x, wid = tid >> 5, lane = tid & 31;
    const int g = lane >> 2, tig = lane & 3, wm = wid >> 2, wn = wid & 3;
#pragma unroll
    for (int mt = 0; mt < 4; mt++) {
        int m = bm * 128 + wm * 64 + mt * 16 + g;
#pragma unroll
        for (int nt = 0; nt < 4; nt++) {
            int col = bn * 128 + wn * 32 + nt * 8 + tig * 2;
            float* dst0;
            if (bn < 16)      dst0 = g_u + (size_t)m * E_ + col;
            else if (bn < 32) dst0 = g_v + (size_t)m * E_ + (col - E_);
            else              dst0 = g_base + (size_t)m * S_ + (col - 2 * E_);
            size_t rstride = (bn < 32) ? E_ : S_;
#pragma unroll
            for (int h = 0; h < 2; h++) {
                float t0 = acc[mt][nt][h * 2 + 0];
                float t1 = acc[mt][nt][h * 2 + 1];
                float2 o;
                o.x = t0 / (1.0f + expf(-t0));
                o.y = t1 / (1.0f + expf(-t1));
                *(float2*)(dst0 + (size_t)h * 8 * rstride) = o;
            }
        }
    }
}

// ---------------- GEMM2: kernel = relu((qk + wrel)/sqrtS)^2 ----------------
__global__ __launch_bounds__(256)
void gemm2_tc(const float* __restrict__ wrel) {
    GEMM_SMEM
    float acc[4][4][4] = {};
    int b = blockIdx.z, bm = blockIdx.y, bn = blockIdx.x;
    gemm_core_mma(g_q + (size_t)b * L_ * S_ + (size_t)bm * 128 * S_, S_,
                  g_k + (size_t)b * L_ * S_ + (size_t)bn * 128 * S_, S_,
                  S_, acc, sAhi, sAlo, sBhi, sBlo);
    const int tid = threadIdx.x, wid = tid >> 5, lane = tid & 31;
    const int g = lane >> 2, tig = lane & 3, wm = wid >> 2, wn = wid & 3;
    const float inv_sqrtS = 0.08838834764831845f;  // 1/sqrt(128)
#pragma unroll
    for (int mt = 0; mt < 4; mt++) {
#pragma unroll
        for (int h = 0; h < 2; h++) {
            int mi = bm * 128 + wm * 64 + mt * 16 + g + h * 8;
            float* row = g_kern + ((size_t)b * L_ + mi) * L_;
#pragma unroll
            for (int nt = 0; nt < 4; nt++) {
                int nj = bn * 128 + wn * 32 + nt * 8 + tig * 2;
                float2 o;
                float t0 = (acc[mt][nt][h * 2 + 0] + wrel[nj - mi + (L_ - 1)]) * inv_sqrtS;
                float t1 = (acc[mt][nt][h * 2 + 1] + wrel[nj + 1 - mi + (L_ - 1)]) * inv_sqrtS;
                float r0 = fmaxf(t0, 0.0f), r1 = fmaxf(t1, 0.0f);
                o.x = r0 * r0; o.y = r1 * r1;
                *(float2*)(row + nj) = o;
            }
        }
    }
}

// ---------------- GEMM3: attn = u * (kern @ v) -----------------------------
__global__ __launch_bounds__(256)
void gemm3_tc() {
    GEMM_SMEM
    float acc[4][4][4] = {};
    int b = blockIdx.z, bm = blockIdx.y, bn = blockIdx.x;
    gemm_core_mma(g_kern + ((size_t)b * L_ + bm * 128) * L_, L_,
                  g_vT + (size_t)b * E_ * L_ + (size_t)bn * 128 * L_, L_,
                  L_, acc, sAhi, sAlo, sBhi, sBlo);
    const int tid = threadIdx.x, wid = tid >> 5, lane = tid & 31;
    const int g = lane >> 2, tig = lane & 3, wm = wid >> 2, wn = wid & 3;
#pragma unroll
    for (int mt = 0; mt < 4; mt++) {
#pragma unroll
        for (int h = 0; h < 2; h++) {
            int mi = bm * 128 + wm * 64 + mt * 16 + g + h * 8;
            size_t rowoff = ((size_t)b * L_ + mi) * E_;
#pragma unroll
            for (int nt = 0; nt < 4; nt++) {
                int nj = bn * 128 + wn * 32 + nt * 8 + tig * 2;
                float2 uu = *(const float2*)(g_u + rowoff + nj);
                float2 o;
                o.x = uu.x * acc[mt][nt][h * 2 + 0];
                o.y = uu.y * acc[mt][nt][h * 2 + 1];
                *(float2*)(g_attn + rowoff + nj) = o;
            }
        }
    }
}

// ---------------- GEMM4: y = attn @ o_w^T + x*res_scale --------------------
__global__ __launch_bounds__(256)
void gemm4_tc(const float* __restrict__ OW, const float* __restrict__ x,
              const float* __restrict__ res_scale, float* __restrict__ out) {
    GEMM_SMEM
    float acc[4][4][4] = {};
    int bm = blockIdx.y, bn = blockIdx.x;
    gemm_core_mma(g_attn + (size_t)bm * 128 * E_, E_,
                  OW + (size_t)bn * 128 * E_, E_, E_, acc, sAhi, sAlo, sBhi, sBlo);
    const int tid = threadIdx.x, wid = tid >> 5, lane = tid & 31;
    const int g = lane >> 2, tig = lane & 3, wm = wid >> 2, wn = wid & 3;
#pragma unroll
    for (int mt = 0; mt < 4; mt++) {
#pragma unroll
        for (int h = 0; h < 2; h++) {
            int m = bm * 128 + wm * 64 + mt * 16 + g + h * 8;
#pragma unroll
            for (int nt = 0; nt < 4; nt++) {
                int d = bn * 128 + wn * 32 + nt * 8 + tig * 2;
                float2 xv = *(const float2*)(x + (size_t)m * D_ + d);
                float2 rs = *(const float2*)(res_scale + d);
                float2 o;
                o.x = xv.x * rs.x + acc[mt][nt][h * 2 + 0];
                o.y = xv.y * rs.y + acc[mt][nt][h * 2 + 1];
                *(float2*)(out + (size_t)m * D_ + d) = o;
            }
        }
    }
}

// ---------------- elementwise kernels ----------------
__global__ void rmsnorm_kernel(const float* __restrict__ x, const float* __restrict__ g) {
    int row = blockIdx.x;
    const float4* xr = (const float4*)(x + (size_t)row * D_);
    float4 v = xr[threadIdx.x];
    float s = v.x * v.x + v.y * v.y + v.z * v.z + v.w * v.w;
    __shared__ float red[256];
    red[threadIdx.x] = s;
    __syncthreads();
    for (int off = 128; off > 0; off >>= 1) {
        if (threadIdx.x < off) red[threadIdx.x] += red[threadIdx.x + off];
        __syncthreads();
    }
    __shared__ float sc;
    if (threadIdx.x == 0) {
        float norm = sqrtf(red[0]) * 0.03125f;
        sc = g[0] / fmaxf(norm, 1e-5f);
    }
    __syncthreads();
    float scale = sc;
    float4 o;
    o.x = v.x * scale; o.y = v.y * scale; o.z = v.z * scale; o.w = v.w * scale;
    ((float4*)(g_xn + (size_t)row * D_))[threadIdx.x] = o;
}

__global__ void rope_table_kernel() {
    int idx = blockIdx.x * blockDim.x + threadIdx.x;
    int l = idx >> 6;
    int j = idx & 63;
    float inv_freq = (float)pow(10000.0, (double)j * (1.0 / 64.0));
    float a = __fmul_rn((float)l, inv_freq);
    g_sin[idx] = (float)sin((double)a);
    g_cos[idx] = (float)cos((double)a);
}

__global__ void rope_apply_kernel(const float* __restrict__ gamma, const float* __restrict__ beta) {
    int m = blockIdx.x;
    int s = threadIdx.x;
    int l = m & (L_ - 1);
    float b1 = g_base[m * S_ + s];
    float b2 = g_base[m * S_ + s + 64];
    float sn = g_sin[l * 64 + s];
    float cs = g_cos[l * 64 + s];
    float q1 = b1 * gamma[s]      + beta[s];
    float q2 = b2 * gamma[s + 64] + beta[s + 64];
    g_q[m * S_ + s]      = q1 * cs - q2 * sn;
    g_q[m * S_ + s + 64] = q2 * cs + q1 * sn;
    float k1 = b1 * gamma[128 + s]      + beta[128 + s];
    float k2 = b2 * gamma[128 + s + 64] + beta[128 + s + 64];
    g_k[m * S_ + s]      = k1 * cs - k2 * sn;
    g_k[m * S_ + s + 64] = k2 * cs + k1 * sn;
}

__global__ void transpose_v_kernel() {  // g_v [b][l][e] -> g_vT [b][e][l]
    __shared__ float t[32][33];
    int b = blockIdx.z;
    int e0 = blockIdx.x * 32, l0 = blockIdx.y * 32;
#pragma unroll
    for (int i = 0; i < 32; i += 8)
        t[threadIdx.y + i][threadIdx.x] =
            g_v[((size_t)b * L_ + l0 + threadIdx.y + i) * E_ + e0 + threadIdx.x];
    __syncthreads();
#pragma unroll
    for (int i = 0; i < 32; i += 8)
        g_vT[((size_t)b * E_ + e0 + threadIdx.y + i) * L_ + l0 + threadIdx.x] =
            t[threadIdx.x][threadIdx.y + i];
}

// ---------------- launch ----------------
extern "C" void kernel_launch(void* const* d_in, const int* in_sizes, int n_in,
                              void* d_out, int out_size) {
    const float* x         = (const float*)d_in[0];
    const float* g         = (const float*)d_in[1];
    const float* uv_w      = (const float*)d_in[2];
    const float* gamma     = (const float*)d_in[3];
    const float* beta      = (const float*)d_in[4];
    const float* w_rel     = (const float*)d_in[5];
    const float* o_w       = (const float*)d_in[6];
    const float* res_scale = (const float*)d_in[7];
    float* out = (float*)d_out;

    rmsnorm_kernel<<<M_, 256>>>(x, g);
    rope_table_kernel<<<(L_ * 64) / 256, 256>>>();
    gemm1_tc<<<dim3(33, 64), 256>>>(uv_w);
    rope_apply_kernel<<<M_, 64>>>(gamma, beta);
    transpose_v_kernel<<<dim3(E_ / 32, L_ / 32, B_), dim3(32, 8)>>>();
    gemm2_tc<<<dim3(8, 8, 8), 256>>>(w_rel);
    gemm3_tc<<<dim3(16, 8, 8), 256>>>();
    gemm4_tc<<<dim3(8, 64), 256>>>(o_w, x, res_scale, out);
}

// round 6
// speedup vs baseline: 2.6891x; 1.7656x over previous
#include <cuda_runtime.h>
#include <cuda_bf16.h>
#include <math.h>
#include <stdint.h>

// ---------------- problem dims ----------------
#define B_   8
#define L_   1024
#define D_   1024
#define E_   2048
#define S_   128
#define M_   (B_ * L_)        // 8192
#define NUV  (2 * E_ + S_)    // 4224

typedef unsigned short u16;

// ---------------- device scratch (bf16 hi/lo planes + fp32 where needed) ----
__device__ __align__(16) u16  g_xn_h [M_ * D_];
__device__ __align__(16) u16  g_xn_l [M_ * D_];
__device__ __align__(16) u16  g_w1_h [NUV * D_];
__device__ __align__(16) u16  g_w1_l [NUV * D_];
__device__ __align__(16) u16  g_ow_h [D_ * E_];
__device__ __align__(16) u16  g_ow_l [D_ * E_];
__device__ __align__(16) float g_u   [M_ * E_];
__device__ __align__(16) float g_v   [M_ * E_];
__device__ __align__(16) u16  g_vT_h [M_ * E_];
__device__ __align__(16) u16  g_vT_l [M_ * E_];
__device__ __align__(16) float g_base[M_ * S_];
__device__ __align__(16) u16  g_q_h  [M_ * S_];
__device__ __align__(16) u16  g_q_l  [M_ * S_];
__device__ __align__(16) u16  g_k_h  [M_ * S_];
__device__ __align__(16) u16  g_k_l  [M_ * S_];
__device__ __align__(16) u16  g_kn_h [(size_t)B_ * L_ * L_];
__device__ __align__(16) u16  g_kn_l [(size_t)B_ * L_ * L_];
__device__ __align__(16) u16  g_at_h [M_ * E_];
__device__ __align__(16) u16  g_at_l [M_ * E_];
__device__ float g_sin [L_ * 64];
__device__ float g_cos [L_ * 64];

// ---------------- helpers ----------------
__device__ __forceinline__ void split2(float x, float y, uint32_t& hi, uint32_t& lo) {
    float hx = __bfloat162float(__float2bfloat16_rn(x));
    float hy = __bfloat162float(__float2bfloat16_rn(y));
    asm("cvt.rn.bf16x2.f32 %0, %1, %2;" : "=r"(hi) : "f"(hy), "f"(hx));
    float lx = x - hx, ly = y - hy;
    asm("cvt.rn.bf16x2.f32 %0, %1, %2;" : "=r"(lo) : "f"(ly), "f"(lx));
}
__device__ __forceinline__ u16 bf16h(float x) {
    __nv_bfloat16 b = __float2bfloat16_rn(x);
    return *(u16*)&b;
}
__device__ __forceinline__ float bf16tof(u16 v) {
    __nv_bfloat16 b = *(__nv_bfloat16*)&v;
    return __bfloat162float(b);
}
__device__ __forceinline__ void mma_bf16(float* c, const uint32_t* a, const uint32_t* b) {
    asm volatile(
        "mma.sync.aligned.m16n8k16.row.col.f32.bf16.bf16.f32 "
        "{%0,%1,%2,%3}, {%4,%5,%6,%7}, {%8,%9}, {%0,%1,%2,%3};"
        : "+f"(c[0]), "+f"(c[1]), "+f"(c[2]), "+f"(c[3])
        : "r"(a[0]), "r"(a[1]), "r"(a[2]), "r"(a[3]), "r"(b[0]), "r"(b[1]));
}
__device__ __forceinline__ uint32_t smem_u32(const void* p) {
    uint32_t a;
    asm("{ .reg .u64 t; cvta.to.shared.u64 t, %1; cvt.u32.u64 %0, t; }" : "=r"(a) : "l"(p));
    return a;
}
__device__ __forceinline__ void cpa16(uint32_t s, const void* g) {
    asm volatile("cp.async.cg.shared.global [%0], [%1], 16;" :: "r"(s), "l"(g) : "memory");
}
#define CP_COMMIT() asm volatile("cp.async.commit_group;" ::: "memory")
#define CP_WAIT1()  asm volatile("cp.async.wait_group 1;" ::: "memory")
#define CP_WAIT0()  asm volatile("cp.async.wait_group 0;" ::: "memory")

#define STR 40                                // smem row stride (bf16 elems)
#define PLANE_BYTES (128 * STR * 2)           // 10240
#define STAGE_BYTES (4 * PLANE_BYTES)         // 40960
#define SMEM_BYTES  (2 * STAGE_BYTES)         // 81920
#define OFF_AH 0
#define OFF_AL (PLANE_BYTES)
#define OFF_BH (2 * PLANE_BYTES)
#define OFF_BL (3 * PLANE_BYTES)

// ---------------- core: C[128x128] = A[128xK] * B[128xK]^T ------------------
// A/B given as bf16 hi+lo planes, row-major. 256 threads, 8 warps 2x4.
__device__ __forceinline__ void gemm_core_bf16(
    const u16* __restrict__ Ah, const u16* __restrict__ Al, int lda,
    const u16* __restrict__ Bh, const u16* __restrict__ Bl, int ldb,
    int K, float acc[4][4][4], char* smem)
{
    const int tid  = threadIdx.x;
    const int lane = tid & 31;
    const int wid  = tid >> 5;
    const int g    = lane >> 2;
    const int tig  = lane & 3;
    const int wm   = wid >> 2;
    const int wn   = wid & 3;
    uint32_t su = smem_u32(smem);

    // per-thread load coords: 512 16B-chunks per plane, 2 per thread
    const int i0 = tid, i1 = tid + 256;
    const int r0 = i0 >> 2, c0 = (i0 & 3) * 8;
    const int r1 = i1 >> 2, c1 = (i1 & 3) * 8;
    const uint32_t so0 = (uint32_t)(r0 * (STR * 2) + (i0 & 3) * 16);
    const uint32_t so1 = (uint32_t)(r1 * (STR * 2) + (i1 & 3) * 16);

    const int NC = K >> 5;
    // prologue: chunk 0 -> stage 0
    {
        uint32_t st = su;
        cpa16(st + OFF_AH + so0, Ah + (size_t)r0 * lda + c0);
        cpa16(st + OFF_AH + so1, Ah + (size_t)r1 * lda + c1);
        cpa16(st + OFF_AL + so0, Al + (size_t)r0 * lda + c0);
        cpa16(st + OFF_AL + so1, Al + (size_t)r1 * lda + c1);
        cpa16(st + OFF_BH + so0, Bh + (size_t)r0 * ldb + c0);
        cpa16(st + OFF_BH + so1, Bh + (size_t)r1 * ldb + c1);
        cpa16(st + OFF_BL + so0, Bl + (size_t)r0 * ldb + c0);
        cpa16(st + OFF_BL + so1, Bl + (size_t)r1 * ldb + c1);
        CP_COMMIT();
    }

    for (int c = 0; c < NC; c++) {
        if (c + 1 < NC) {
            int k0 = (c + 1) * 32;
            uint32_t st = su + ((c + 1) & 1) * STAGE_BYTES;
            cpa16(st + OFF_AH + so0, Ah + (size_t)r0 * lda + k0 + c0);
            cpa16(st + OFF_AH + so1, Ah + (size_t)r1 * lda + k0 + c1);
            cpa16(st + OFF_AL + so0, Al + (size_t)r0 * lda + k0 + c0);
            cpa16(st + OFF_AL + so1, Al + (size_t)r1 * lda + k0 + c1);
            cpa16(st + OFF_BH + so0, Bh + (size_t)r0 * ldb + k0 + c0);
            cpa16(st + OFF_BH + so1, Bh + (size_t)r1 * ldb + k0 + c1);
            cpa16(st + OFF_BL + so0, Bl + (size_t)r0 * ldb + k0 + c0);
            cpa16(st + OFF_BL + so1, Bl + (size_t)r1 * ldb + k0 + c1);
            CP_COMMIT();
            CP_WAIT1();
        } else {
            CP_WAIT0();
        }
        __syncthreads();

        char* stg = smem + (c & 1) * STAGE_BYTES;
        const u16* sAh = (const u16*)(stg + OFF_AH);
        const u16* sAl = (const u16*)(stg + OFF_AL);
        const u16* sBh = (const u16*)(stg + OFF_BH);
        const u16* sBl = (const u16*)(stg + OFF_BL);

#pragma unroll
        for (int ks = 0; ks < 2; ks++) {
            const int kb = ks * 16;
            uint32_t ah[4][4], al[4][4], bh[4][2], bl[4][2];
#pragma unroll
            for (int mt = 0; mt < 4; mt++) {
                int base = (wm * 64 + mt * 16 + g) * STR + kb + tig * 2;
                ah[mt][0] = *(uint32_t*)&sAh[base];
                ah[mt][1] = *(uint32_t*)&sAh[base + 8 * STR];
                ah[mt][2] = *(uint32_t*)&sAh[base + 8];
                ah[mt][3] = *(uint32_t*)&sAh[base + 8 * STR + 8];
                al[mt][0] = *(uint32_t*)&sAl[base];
                al[mt][1] = *(uint32_t*)&sAl[base + 8 * STR];
                al[mt][2] = *(uint32_t*)&sAl[base + 8];
                al[mt][3] = *(uint32_t*)&sAl[base + 8 * STR + 8];
            }
#pragma unroll
            for (int nt = 0; nt < 4; nt++) {
                int base = (wn * 32 + nt * 8 + g) * STR + kb + tig * 2;
                bh[nt][0] = *(uint32_t*)&sBh[base];
                bh[nt][1] = *(uint32_t*)&sBh[base + 8];
                bl[nt][0] = *(uint32_t*)&sBl[base];
                bl[nt][1] = *(uint32_t*)&sBl[base + 8];
            }
#pragma unroll
            for (int mt = 0; mt < 4; mt++)
#pragma unroll
                for (int nt = 0; nt < 4; nt++) {
                    mma_bf16(acc[mt][nt], ah[mt], bh[nt]);
                    mma_bf16(acc[mt][nt], ah[mt], bl[nt]);
                    mma_bf16(acc[mt][nt], al[mt], bh[nt]);
                }
        }
        __syncthreads();
    }
}

// fragment (mt,nt,h) coords: row = wm*64+mt*16+g+h*8, col = wn*32+nt*8+tig*2 (+1)

// ---------------- GEMM1: uv = silu(xn @ uv_w^T), split u/v/base ------------
__global__ __launch_bounds__(256)
void gemm1_tc() {
    extern __shared__ char smem[];
    float acc[4][4][4] = {};
    int bm = blockIdx.y, bn = blockIdx.x;
    gemm_core_bf16(g_xn_h + (size_t)bm * 128 * D_, g_xn_l + (size_t)bm * 128 * D_, D_,
                   g_w1_h + (size_t)bn * 128 * D_, g_w1_l + (size_t)bn * 128 * D_, D_,
                   D_, acc, smem);
    const int tid = threadIdx.x, wid = tid >> 5, lane = tid & 31;
    const int g = lane >> 2, tig = lane & 3, wm = wid >> 2, wn = wid & 3;
#pragma unroll
    for (int mt = 0; mt < 4; mt++) {
#pragma unroll
        for (int h = 0; h < 2; h++) {
            int m = bm * 128 + wm * 64 + mt * 16 + g + h * 8;
#pragma unroll
            for (int nt = 0; nt < 4; nt++) {
                int col = bn * 128 + wn * 32 + nt * 8 + tig * 2;
                float t0 = acc[mt][nt][h * 2 + 0];
                float t1 = acc[mt][nt][h * 2 + 1];
                float2 o;
                o.x = t0 / (1.0f + expf(-t0));
                o.y = t1 / (1.0f + expf(-t1));
                if (bn < 16)      *(float2*)(g_u + (size_t)m * E_ + col) = o;
                else if (bn < 32) *(float2*)(g_v + (size_t)m * E_ + (col - E_)) = o;
                else              *(float2*)(g_base + (size_t)m * S_ + (col - 2 * E_)) = o;
            }
        }
    }
}

// ---------------- GEMM2: kern = relu((qk + wrel)/sqrtS)^2 -> bf16 planes ---
__global__ __launch_bounds__(256)
void gemm2_tc(const float* __restrict__ wrel) {
    extern __shared__ char smem[];
    float acc[4][4][4] = {};
    int b = blockIdx.z, bm = blockIdx.y, bn = blockIdx.x;
    size_t ao = (size_t)b * L_ * S_ + (size_t)bm * 128 * S_;
    size_t bo = (size_t)b * L_ * S_ + (size_t)bn * 128 * S_;
    gemm_core_bf16(g_q_h + ao, g_q_l + ao, S_, g_k_h + bo, g_k_l + bo, S_, S_, acc, smem);
    const int tid = threadIdx.x, wid = tid >> 5, lane = tid & 31;
    const int g = lane >> 2, tig = lane & 3, wm = wid >> 2, wn = wid & 3;
    const float inv_sqrtS = 0.08838834764831845f;
#pragma unroll
    for (int mt = 0; mt < 4; mt++) {
#pragma unroll
        for (int h = 0; h < 2; h++) {
            int mi = bm * 128 + wm * 64 + mt * 16 + g + h * 8;
            size_t rowoff = ((size_t)b * L_ + mi) * L_;
#pragma unroll
            for (int nt = 0; nt < 4; nt++) {
                int nj = bn * 128 + wn * 32 + nt * 8 + tig * 2;
                float t0 = (acc[mt][nt][h * 2 + 0] + wrel[nj - mi + (L_ - 1)]) * inv_sqrtS;
                float t1 = (acc[mt][nt][h * 2 + 1] + wrel[nj + 1 - mi + (L_ - 1)]) * inv_sqrtS;
                float r0 = fmaxf(t0, 0.0f), r1 = fmaxf(t1, 0.0f);
                uint32_t hh, ll;
                split2(r0 * r0, r1 * r1, hh, ll);
                *(uint32_t*)&g_kn_h[rowoff + nj] = hh;
                *(uint32_t*)&g_kn_l[rowoff + nj] = ll;
            }
        }
    }
}

// ---------------- GEMM3: attn = u * (kern @ v) -> bf16 planes --------------
__global__ __launch_bounds__(256)
void gemm3_tc() {
    extern __shared__ char smem[];
    float acc[4][4][4] = {};
    int b = blockIdx.z, bm = blockIdx.y, bn = blockIdx.x;
    size_t ao = ((size_t)b * L_ + bm * 128) * L_;
    size_t bo = (size_t)b * E_ * L_ + (size_t)bn * 128 * L_;
    gemm_core_bf16(g_kn_h + ao, g_kn_l + ao, L_, g_vT_h + bo, g_vT_l + bo, L_, L_, acc, smem);
    const int tid = threadIdx.x, wid = tid >> 5, lane = tid & 31;
    const int g = lane >> 2, tig = lane & 3, wm = wid >> 2, wn = wid & 3;
#pragma unroll
    for (int mt = 0; mt < 4; mt++) {
#pragma unroll
        for (int h = 0; h < 2; h++) {
            int mi = bm * 128 + wm * 64 + mt * 16 + g + h * 8;
            size_t rowoff = ((size_t)b * L_ + mi) * E_;
#pragma unroll
            for (int nt = 0; nt < 4; nt++) {
                int nj = bn * 128 + wn * 32 + nt * 8 + tig * 2;
                float2 uu = *(const float2*)(g_u + rowoff + nj);
                uint32_t hh, ll;
                split2(uu.x * acc[mt][nt][h * 2 + 0], uu.y * acc[mt][nt][h * 2 + 1], hh, ll);
                *(uint32_t*)&g_at_h[rowoff + nj] = hh;
                *(uint32_t*)&g_at_l[rowoff + nj] = ll;
            }
        }
    }
}

// ---------------- GEMM4: y = attn @ o_w^T + x*res_scale --------------------
__global__ __launch_bounds__(256)
void gemm4_tc(const float* __restrict__ x, const float* __restrict__ res_scale,
              float* __restrict__ out) {
    extern __shared__ char smem[];
    float acc[4][4][4] = {};
    int bm = blockIdx.y, bn = blockIdx.x;
    gemm_core_bf16(g_at_h + (size_t)bm * 128 * E_, g_at_l + (size_t)bm * 128 * E_, E_,
                   g_ow_h + (size_t)bn * 128 * E_, g_ow_l + (size_t)bn * 128 * E_, E_,
                   E_, acc, smem);
    const int tid = threadIdx.x, wid = tid >> 5, lane = tid & 31;
    const int g = lane >> 2, tig = lane & 3, wm = wid >> 2, wn = wid & 3;
#pragma unroll
    for (int mt = 0; mt < 4; mt++) {
#pragma unroll
        for (int h = 0; h < 2; h++) {
            int m = bm * 128 + wm * 64 + mt * 16 + g + h * 8;
#pragma unroll
            for (int nt = 0; nt < 4; nt++) {
                int d = bn * 128 + wn * 32 + nt * 8 + tig * 2;
                float2 xv = *(const float2*)(x + (size_t)m * D_ + d);
                float2 rs = *(const float2*)(res_scale + d);
                float2 o;
                o.x = xv.x * rs.x + acc[mt][nt][h * 2 + 0];
                o.y = xv.y * rs.y + acc[mt][nt][h * 2 + 1];
                *(float2*)(out + (size_t)m * D_ + d) = o;
            }
        }
    }
}

// ---------------- producers / elementwise ----------------
__global__ void rmsnorm_kernel(const float* __restrict__ x, const float* __restrict__ g) {
    int row = blockIdx.x;
    const float4* xr = (const float4*)(x + (size_t)row * D_);
    float4 v = xr[threadIdx.x];
    float s = v.x * v.x + v.y * v.y + v.z * v.z + v.w * v.w;
    __shared__ float red[256];
    red[threadIdx.x] = s;
    __syncthreads();
    for (int off = 128; off > 0; off >>= 1) {
        if (threadIdx.x < off) red[threadIdx.x] += red[threadIdx.x + off];
        __syncthreads();
    }
    __shared__ float sc;
    if (threadIdx.x == 0) {
        float norm = sqrtf(red[0]) * 0.03125f;
        sc = g[0] / fmaxf(norm, 1e-5f);
    }
    __syncthreads();
    float scale = sc;
    uint32_t h0, l0, h1, l1;
    split2(v.x * scale, v.y * scale, h0, l0);
    split2(v.z * scale, v.w * scale, h1, l1);
    size_t o = (size_t)row * D_ + threadIdx.x * 4;
    *(uint32_t*)&g_xn_h[o]     = h0;
    *(uint32_t*)&g_xn_h[o + 2] = h1;
    *(uint32_t*)&g_xn_l[o]     = l0;
    *(uint32_t*)&g_xn_l[o + 2] = l1;
}

__global__ void convert_pair_kernel(const float* __restrict__ src,
                                    u16* __restrict__ dh, u16* __restrict__ dl) {
    int i = (blockIdx.x * blockDim.x + threadIdx.x) * 2;
    float2 v = *(const float2*)(src + i);
    uint32_t h, l;
    split2(v.x, v.y, h, l);
    *(uint32_t*)&dh[i] = h;
    *(uint32_t*)&dl[i] = l;
}

__global__ void rope_table_kernel() {
    int idx = blockIdx.x * blockDim.x + threadIdx.x;
    int l = idx >> 6;
    int j = idx & 63;
    float inv_freq = (float)pow(10000.0, (double)j * (1.0 / 64.0));
    float a = __fmul_rn((float)l, inv_freq);
    g_sin[idx] = (float)sin((double)a);
    g_cos[idx] = (float)cos((double)a);
}

__global__ void rope_apply_kernel(const float* __restrict__ gamma, const float* __restrict__ beta) {
    int m = blockIdx.x;
    int s = threadIdx.x;
    int l = m & (L_ - 1);
    float b1 = g_base[m * S_ + s];
    float b2 = g_base[m * S_ + s + 64];
    float sn = g_sin[l * 64 + s];
    float cs = g_cos[l * 64 + s];
    float q1 = b1 * gamma[s]      + beta[s];
    float q2 = b2 * gamma[s + 64] + beta[s + 64];
    float qa = q1 * cs - q2 * sn;
    float qb = q2 * cs + q1 * sn;
    float k1 = b1 * gamma[128 + s]      + beta[128 + s];
    float k2 = b2 * gamma[128 + s + 64] + beta[128 + s + 64];
    float ka = k1 * cs - k2 * sn;
    float kb = k2 * cs + k1 * sn;
    int i0 = m * S_ + s, i1 = m * S_ + s + 64;
    u16 h;
    h = bf16h(qa); g_q_h[i0] = h; g_q_l[i0] = bf16h(qa - bf16tof(h));
    h = bf16h(qb); g_q_h[i1] = h; g_q_l[i1] = bf16h(qb - bf16tof(h));
    h = bf16h(ka); g_k_h[i0] = h; g_k_l[i0] = bf16h(ka - bf16tof(h));
    h = bf16h(kb); g_k_h[i1] = h; g_k_l[i1] = bf16h(kb - bf16tof(h));
}

__global__ void transpose_v_kernel() {  // g_v [b][l][e] -> vT planes [b][e][l]
    __shared__ float t[32][33];
    int b = blockIdx.z;
    int e0 = blockIdx.x * 32, l0 = blockIdx.y * 32;
#pragma unroll
    for (int i = 0; i < 32; i += 8)
        t[threadIdx.y + i][threadIdx.x] =
            g_v[((size_t)b * L_ + l0 + threadIdx.y + i) * E_ + e0 + threadIdx.x];
    __syncthreads();
#pragma unroll
    for (int i = 0; i < 32; i += 8) {
        float val = t[threadIdx.x][threadIdx.y + i];
        size_t o = ((size_t)b * E_ + e0 + threadIdx.y + i) * L_ + l0 + threadIdx.x;
        u16 h = bf16h(val);
        g_vT_h[o] = h;
        g_vT_l[o] = bf16h(val - bf16tof(h));
    }
}

// ---------------- launch ----------------
extern "C" void kernel_launch(void* const* d_in, const int* in_sizes, int n_in,
                              void* d_out, int out_size) {
    const float* x         = (const float*)d_in[0];
    const float* g         = (const float*)d_in[1];
    const float* uv_w      = (const float*)d_in[2];
    const float* gamma     = (const float*)d_in[3];
    const float* beta      = (const float*)d_in[4];
    const float* w_rel     = (const float*)d_in[5];
    const float* o_w       = (const float*)d_in[6];
    const float* res_scale = (const float*)d_in[7];
    float* out = (float*)d_out;

    static int attr_done = 0;
    if (!attr_done) {
        cudaFuncSetAttribute(gemm1_tc, cudaFuncAttributeMaxDynamicSharedMemorySize, SMEM_BYTES);
        cudaFuncSetAttribute(gemm2_tc, cudaFuncAttributeMaxDynamicSharedMemorySize, SMEM_BYTES);
        cudaFuncSetAttribute(gemm3_tc, cudaFuncAttributeMaxDynamicSharedMemorySize, SMEM_BYTES);
        cudaFuncSetAttribute(gemm4_tc, cudaFuncAttributeMaxDynamicSharedMemorySize, SMEM_BYTES);
        attr_done = 1;
    }

    u16* w1h; u16* w1l; u16* owh; u16* owl;
    cudaGetSymbolAddress((void**)&w1h, g_w1_h);
    cudaGetSymbolAddress((void**)&w1l, g_w1_l);
    cudaGetSymbolAddress((void**)&owh, g_ow_h);
    cudaGetSymbolAddress((void**)&owl, g_ow_l);

    rmsnorm_kernel<<<M_, 256>>>(x, g);
    rope_table_kernel<<<(L_ * 64) / 256, 256>>>();
    convert_pair_kernel<<<(NUV * D_) / 512, 256>>>(uv_w, w1h, w1l);
    convert_pair_kernel<<<(D_ * E_) / 512, 256>>>(o_w, owh, owl);
    gemm1_tc<<<dim3(33, 64), 256, SMEM_BYTES>>>();
    rope_apply_kernel<<<M_, 64>>>(gamma, beta);
    transpose_v_kernel<<<dim3(E_ / 32, L_ / 32, B_), dim3(32, 8)>>>();
    gemm2_tc<<<dim3(8, 8, 8), 256, SMEM_BYTES>>>(w_rel);
    gemm3_tc<<<dim3(16, 8, 8), 256, SMEM_BYTES>>>();
    gemm4_tc<<<dim3(8, 64), 256, SMEM_BYTES>>>(x, res_scale, out);
}